// round 1
// baseline (speedup 1.0000x reference)
#include <cuda_runtime.h>
#include <math.h>

#define B_ 8
#define S_ 2048
#define D_ 1024
#define H_ 64
#define BS_ (B_*S_)

// Scratch for projected Q, K, V (4 MB each) — __device__ globals, allocation-free.
__device__ float g_q[BS_ * H_];
__device__ float g_k[BS_ * H_];
__device__ float g_v[BS_ * H_];

// ---------------------------------------------------------------------------
// Kernel 1: fused QKV projection.
//   C[16384, 192] = X[16384, 1024] @ [Wq | Wk | Wv]   (each [1024, 64])
// Block tile: 64 rows x 192 cols, K-chunk 16. 256 threads, thread tile 4x12.
// ---------------------------------------------------------------------------
__global__ __launch_bounds__(256) void qkv_kernel(
    const float* __restrict__ X,
    const float* __restrict__ Wq,
    const float* __restrict__ Wk,
    const float* __restrict__ Wv)
{
    __shared__ float Xs[64][17];    // pad to dodge bank conflicts
    __shared__ float Ws[16][192];

    const int t    = threadIdx.x;
    const int row0 = blockIdx.x * 64;
    const int tr   = t >> 4;        // 0..15  (x4 rows)
    const int tc   = t & 15;        // 0..15  (x12 cols)

    float acc[4][12];
#pragma unroll
    for (int i = 0; i < 4; i++)
#pragma unroll
        for (int j = 0; j < 12; j++) acc[i][j] = 0.f;

    for (int k0 = 0; k0 < D_; k0 += 16) {
        // Load X tile [64 x 16] (float4, coalesced)
        {
            int row = t >> 2;
            int kp  = (t & 3) << 2;
            float4 x = *(const float4*)(X + (size_t)(row0 + row) * D_ + k0 + kp);
            Xs[row][kp + 0] = x.x;
            Xs[row][kp + 1] = x.y;
            Xs[row][kp + 2] = x.z;
            Xs[row][kp + 3] = x.w;
        }
        // Load W tile [16 x 192] (float4, coalesced within each matrix)
#pragma unroll
        for (int n = 0; n < 3; n++) {
            int i4 = t + 256 * n;           // 0..767
            int kk = i4 / 48;               // 0..15
            int c  = (i4 % 48) << 2;        // 0..188, step 4
            const float* W = (c < 64) ? Wq : (c < 128 ? Wk : Wv);
            float4 wv = *(const float4*)(W + (size_t)(k0 + kk) * H_ + (c & 63));
            *(float4*)&Ws[kk][c] = wv;
        }
        __syncthreads();

#pragma unroll
        for (int kk = 0; kk < 16; kk++) {
            float aa[4];
#pragma unroll
            for (int i = 0; i < 4; i++) aa[i] = Xs[tr * 4 + i][kk];
            float4 b0 = *(float4*)&Ws[kk][tc * 12 + 0];
            float4 b1 = *(float4*)&Ws[kk][tc * 12 + 4];
            float4 b2 = *(float4*)&Ws[kk][tc * 12 + 8];
            float bb[12] = {b0.x, b0.y, b0.z, b0.w,
                            b1.x, b1.y, b1.z, b1.w,
                            b2.x, b2.y, b2.z, b2.w};
#pragma unroll
            for (int i = 0; i < 4; i++)
#pragma unroll
                for (int j = 0; j < 12; j++)
                    acc[i][j] = fmaf(aa[i], bb[j], acc[i][j]);
        }
        __syncthreads();
    }

    // Writeback: cols [0,64)->Q, [64,128)->K, [128,192)->V
#pragma unroll
    for (int j = 0; j < 12; j++) {
        int c = tc * 12 + j;
        float* dst = (c < 64) ? g_q : (c < 128 ? g_k : g_v);
        int h = c & 63;
#pragma unroll
        for (int i = 0; i < 4; i++)
            dst[(size_t)(row0 + tr * 4 + i) * H_ + h] = acc[i][j];
    }
}

// ---------------------------------------------------------------------------
// Kernel 2: causal flash attention, fp32.
// Block: one (batch, 64-query tile). 256 threads = 8 warps; warp owns 8 rows.
// Lane l owns output cols {l, l+32}. K stored transposed [d][k] (pad 65).
// ---------------------------------------------------------------------------
struct SmemAttn {
    float Qs[64][64];    // [q][d], broadcast reads only
    float KsT[64][65];   // [d][k]
    float Vs[64][64];    // [k][h]
    float Ps[64][64];    // [q][k], warp-private rows
};
#define ATTN_SMEM_BYTES ((int)sizeof(SmemAttn))

extern __shared__ float attn_smem_raw[];

__global__ __launch_bounds__(256) void attn_kernel(float* __restrict__ out)
{
    SmemAttn* sm = (SmemAttn*)attn_smem_raw;
    const int qt   = (int)(gridDim.x - 1 - blockIdx.x);  // heavy tiles first
    const int b    = blockIdx.y;
    const int t    = threadIdx.x;
    const int w    = t >> 5;
    const int lane = t & 31;
    const int r0   = w * 8;                               // warp's first row

    // Load Q tile (4096 floats, float4 coalesced)
    const float* Qg = g_q + ((size_t)b * S_ + (size_t)qt * 64) * H_;
#pragma unroll
    for (int n = 0; n < 4; n++) {
        int i4 = t + 256 * n;
        ((float4*)&sm->Qs[0][0])[i4] = ((const float4*)Qg)[i4];
    }

    float acc0[8], acc1[8], mrow[8], lrow[8];
#pragma unroll
    for (int r = 0; r < 8; r++) {
        acc0[r] = 0.f; acc1[r] = 0.f;
        mrow[r] = -INFINITY; lrow[r] = 0.f;
    }

    const float scale = 0.03125f;  // 1024^-0.5

    for (int kt = 0; kt <= qt; kt++) {
        __syncthreads();  // prior tile's smem reads done (also guards Q load on kt=0)

        const float* Kg = g_k + ((size_t)b * S_ + (size_t)kt * 64) * H_;
        const float* Vg = g_v + ((size_t)b * S_ + (size_t)kt * 64) * H_;
#pragma unroll
        for (int n = 0; n < 4; n++) {
            int i4 = t + 256 * n;
            int k  = i4 >> 4;
            int dp = (i4 & 15) << 2;
            float4 kv = ((const float4*)Kg)[i4];
            sm->KsT[dp + 0][k] = kv.x;
            sm->KsT[dp + 1][k] = kv.y;
            sm->KsT[dp + 2][k] = kv.z;
            sm->KsT[dp + 3][k] = kv.w;
            ((float4*)&sm->Vs[0][0])[i4] = ((const float4*)Vg)[i4];
        }
        __syncthreads();

        // ---- scores: S = Q K^T (lane: keys {lane, lane+32}, rows r0..r0+7)
        float s0[8], s1[8];
#pragma unroll
        for (int r = 0; r < 8; r++) { s0[r] = 0.f; s1[r] = 0.f; }
#pragma unroll 4
        for (int d = 0; d < 64; d += 4) {
            float k00 = sm->KsT[d + 0][lane], k01 = sm->KsT[d + 1][lane];
            float k02 = sm->KsT[d + 2][lane], k03 = sm->KsT[d + 3][lane];
            float k10 = sm->KsT[d + 0][lane + 32], k11 = sm->KsT[d + 1][lane + 32];
            float k12 = sm->KsT[d + 2][lane + 32], k13 = sm->KsT[d + 3][lane + 32];
#pragma unroll
            for (int r = 0; r < 8; r++) {
                float4 q = *(const float4*)&sm->Qs[r0 + r][d];
                s0[r] = fmaf(q.x, k00, fmaf(q.y, k01, fmaf(q.z, k02, fmaf(q.w, k03, s0[r]))));
                s1[r] = fmaf(q.x, k10, fmaf(q.y, k11, fmaf(q.z, k12, fmaf(q.w, k13, s1[r]))));
            }
        }

        // ---- online softmax update
        const bool diag = (kt == qt);
        const int kg0 = kt * 64 + lane;
        const int kg1 = kg0 + 32;
#pragma unroll
        for (int r = 0; r < 8; r++) {
            int qg = qt * 64 + r0 + r;
            float v0 = s0[r] * scale;
            float v1 = s1[r] * scale;
            if (diag) {
                if (kg0 > qg) v0 = -1e30f;
                if (kg1 > qg) v1 = -1e30f;
            }
            float mx = fmaxf(v0, v1);
            mx = fmaxf(mx, __shfl_xor_sync(0xffffffffu, mx, 16));
            mx = fmaxf(mx, __shfl_xor_sync(0xffffffffu, mx, 8));
            mx = fmaxf(mx, __shfl_xor_sync(0xffffffffu, mx, 4));
            mx = fmaxf(mx, __shfl_xor_sync(0xffffffffu, mx, 2));
            mx = fmaxf(mx, __shfl_xor_sync(0xffffffffu, mx, 1));
            float mnew = fmaxf(mrow[r], mx);
            float p0   = __expf(v0 - mnew);
            float p1   = __expf(v1 - mnew);
            float corr = __expf(mrow[r] - mnew);   // 0 when mrow = -inf
            float ps = p0 + p1;
            ps += __shfl_xor_sync(0xffffffffu, ps, 16);
            ps += __shfl_xor_sync(0xffffffffu, ps, 8);
            ps += __shfl_xor_sync(0xffffffffu, ps, 4);
            ps += __shfl_xor_sync(0xffffffffu, ps, 2);
            ps += __shfl_xor_sync(0xffffffffu, ps, 1);
            lrow[r] = lrow[r] * corr + ps;
            acc0[r] *= corr;
            acc1[r] *= corr;
            mrow[r] = mnew;
            sm->Ps[r0 + r][lane]      = p0;
            sm->Ps[r0 + r][lane + 32] = p1;
        }
        __syncwarp();  // Ps rows are warp-private; publish across lanes

        // ---- acc += P V  (lane: h in {lane, lane+32})
#pragma unroll 4
        for (int k = 0; k < 64; k += 4) {
            float v00 = sm->Vs[k + 0][lane], v01 = sm->Vs[k + 1][lane];
            float v02 = sm->Vs[k + 2][lane], v03 = sm->Vs[k + 3][lane];
            float v10 = sm->Vs[k + 0][lane + 32], v11 = sm->Vs[k + 1][lane + 32];
            float v12 = sm->Vs[k + 2][lane + 32], v13 = sm->Vs[k + 3][lane + 32];
#pragma unroll
            for (int r = 0; r < 8; r++) {
                float4 p = *(const float4*)&sm->Ps[r0 + r][k];
                acc0[r] = fmaf(p.x, v00, fmaf(p.y, v01, fmaf(p.z, v02, fmaf(p.w, v03, acc0[r]))));
                acc1[r] = fmaf(p.x, v10, fmaf(p.y, v11, fmaf(p.z, v12, fmaf(p.w, v13, acc1[r]))));
            }
        }
    }

    // ---- epilogue: out = acc / l
    float* O = out + ((size_t)b * S_ + (size_t)qt * 64) * H_;
#pragma unroll
    for (int r = 0; r < 8; r++) {
        float inv = 1.0f / lrow[r];   // identical across lanes
        O[(r0 + r) * H_ + lane]      = acc0[r] * inv;
        O[(r0 + r) * H_ + lane + 32] = acc1[r] * inv;
    }
}

// ---------------------------------------------------------------------------
// kernel_launch — graph-capturable, allocation-free.
// Input order (metadata): idx, Wk, Wq, Wv. Output: [8, 2048, 64] f32.
// ---------------------------------------------------------------------------
extern "C" void kernel_launch(void* const* d_in, const int* in_sizes, int n_in,
                              void* d_out, int out_size)
{
    const float* X  = (const float*)d_in[0];
    const float* Wk = (const float*)d_in[1];
    const float* Wq = (const float*)d_in[2];
    const float* Wv = (const float*)d_in[3];
    float* out = (float*)d_out;

    qkv_kernel<<<BS_ / 64, 256>>>(X, Wq, Wk, Wv);

    cudaFuncSetAttribute(attn_kernel,
                         cudaFuncAttributeMaxDynamicSharedMemorySize,
                         ATTN_SMEM_BYTES);
    attn_kernel<<<dim3(S_ / 64, B_), 256, ATTN_SMEM_BYTES>>>(out);
}